// round 8
// baseline (speedup 1.0000x reference)
#include <cuda_runtime.h>

#define N_NODES 120000
#define N_EDGES 1000000
#define DIM 64
#define N_LAYERS 3
#define OUT_STRIDE 256   // (N_LAYERS+1)*DIM
#define NB 4             // nodes per warp
#define SCAN_TB 1024
#define SCAN_BLOCKS ((N_NODES + SCAN_TB - 1) / SCAN_TB)  // 118

// ---------------- scratch ----------------
__device__ int   g_degcol[N_NODES];
__device__ int   g_degrow[N_NODES];
__device__ float g_dinv[N_NODES];
__device__ int   g_rowptr[N_NODES + 1];
__device__ int   g_cursor[N_NODES];
__device__ int   g_blocksum[SCAN_BLOCKS];
__device__ int2  g_edges[N_EDGES];   // CSR-ordered {col, __float_as_int(norm)}

// ---------------- setup ----------------
__global__ void init_kernel() {
    int i = blockIdx.x * blockDim.x + threadIdx.x;
    if (i < N_NODES) { g_degcol[i] = 0; g_degrow[i] = 0; }
}

__global__ void hist_kernel(const int* __restrict__ ei) {
    int e = blockIdx.x * blockDim.x + threadIdx.x;
    if (e >= N_EDGES) return;
    atomicAdd(&g_degrow[ei[e]], 1);
    atomicAdd(&g_degcol[ei[N_EDGES + e]], 1);
}

__global__ void dinv_kernel() {
    int i = blockIdx.x * blockDim.x + threadIdx.x;
    if (i >= N_NODES) return;
    int d = g_degcol[i];
    g_dinv[i] = (d > 0) ? rsqrtf((float)d) : 0.f;
}

__global__ void scan_a_kernel() {
    __shared__ int wsum[32];
    int tid = threadIdx.x, lane = tid & 31, wid = tid >> 5;
    int i = blockIdx.x * SCAN_TB + tid;
    int v = (i < N_NODES) ? g_degrow[i] : 0;
    int x = v;
#pragma unroll
    for (int off = 1; off < 32; off <<= 1) {
        int y = __shfl_up_sync(0xffffffffu, x, off);
        if (lane >= off) x += y;
    }
    if (lane == 31) wsum[wid] = x;
    __syncthreads();
    if (wid == 0) {
        int w = wsum[lane];
#pragma unroll
        for (int off = 1; off < 32; off <<= 1) {
            int y = __shfl_up_sync(0xffffffffu, w, off);
            if (lane >= off) w += y;
        }
        wsum[lane] = w;
    }
    __syncthreads();
    int excl = ((wid > 0) ? wsum[wid - 1] : 0) + x - v;
    if (i < N_NODES) g_rowptr[i] = excl;
    if (tid == SCAN_TB - 1) g_blocksum[blockIdx.x] = excl + v;
}

__global__ void scan_b_kernel() {
    __shared__ int ws[4];
    int tid = threadIdx.x, lane = tid & 31, wid = tid >> 5;
    int v = (tid < SCAN_BLOCKS) ? g_blocksum[tid] : 0;
    int x = v;
#pragma unroll
    for (int off = 1; off < 32; off <<= 1) {
        int y = __shfl_up_sync(0xffffffffu, x, off);
        if (lane >= off) x += y;
    }
    if (lane == 31) ws[wid] = x;
    __syncthreads();
    int carry = 0;
    for (int k = 0; k < wid; k++) carry += ws[k];
    if (tid < SCAN_BLOCKS) g_blocksum[tid] = carry + x - v;
}

__global__ void scan_c_kernel() {
    int i = blockIdx.x * SCAN_TB + threadIdx.x;
    if (i < N_NODES) {
        int r = g_rowptr[i] + g_blocksum[blockIdx.x];
        g_rowptr[i] = r;
        g_cursor[i] = r;
    }
    if (i == 0) g_rowptr[N_NODES] = N_EDGES;
}

__global__ void scatter_kernel(const int* __restrict__ ei) {
    int e = blockIdx.x * blockDim.x + threadIdx.x;
    if (e >= N_EDGES) return;
    int r = ei[e];
    int c = ei[N_EDGES + e];
    float nv = g_dinv[r] * g_dinv[c];
    int pos = atomicAdd(&g_cursor[r], 1);
    g_edges[pos] = make_int2(c, __float_as_int(nv));
}

__global__ void copy_emb_kernel(const float* __restrict__ emb, float* __restrict__ out) {
    int i = blockIdx.x * blockDim.x + threadIdx.x;
    if (i >= N_NODES * (DIM / 4)) return;
    int r = i >> 4;
    int q = i & 15;
    ((float4*)out)[(size_t)r * (OUT_STRIDE / 4) + q] = ((const float4*)emb)[i];
}

// ---------------- fused layer: CSR gather + shuffle GEMV + LeakyReLU ----------------
// 256 threads (8 warps); each warp owns NB=4 nodes. Lane handles dims {2*lane, 2*lane+1}.
// agg2 = xr (.) agg1 -> one gathered accumulator. launch_bounds(256,4) targets 32 warps/SM.
__global__ __launch_bounds__(256, 4) void fused_layer_kernel(
    const float* __restrict__ W1, const float* __restrict__ b1,
    const float* __restrict__ W2, const float* __restrict__ b2,
    float* __restrict__ out, int loff) {
    __shared__ float sW1[DIM * DIM];   // sW1[k*64 + d] = W1[d][k]
    __shared__ float sW2[DIM * DIM];
    __shared__ float sb[DIM];

    int tid = threadIdx.x;
    for (int i = tid; i < DIM * DIM; i += 256) {
        int d = i >> 6, k = i & 63;
        sW1[k * DIM + d] = W1[i];
        sW2[k * DIM + d] = W2[i];
    }
    if (tid < DIM) sb[tid] = b1[tid] + b2[tid];
    __syncthreads();

    int lane = tid & 31;
    int w = tid >> 5;
    int base = (blockIdx.x * 8 + w) * NB;   // grid exact: base+NB <= N_NODES
    const float* x = out + loff;

    float a1x[NB], a1y[NB], a2x[NB], a2y[NB], sv[NB];
#pragma unroll
    for (int j = 0; j < NB; j++) {
        float ax = 0.f, ay = 0.f, s = 0.f;
        int n = base + j;
        int s0 = g_rowptr[n], s1 = g_rowptr[n + 1];
        float2 xr = *(const float2*)(x + (size_t)n * OUT_STRIDE + 2 * lane);
        for (int e = s0; e < s1; e++) {
            int2 rec = g_edges[e];
            float nv = __int_as_float(rec.y);
            float2 xc = *(const float2*)(x + (size_t)rec.x * OUT_STRIDE + 2 * lane);
            ax += nv * xc.x;
            ay += nv * xc.y;
            s += nv;
        }
        a1x[j] = ax;
        a1y[j] = ay;
        a2x[j] = ax * xr.x;
        a2y[j] = ay * xr.y;
        sv[j] = s;
    }

    float yx[NB], yy[NB];
    float bx = sb[2 * lane], by = sb[2 * lane + 1];
#pragma unroll
    for (int j = 0; j < NB; j++) { yx[j] = sv[j] * bx; yy[j] = sv[j] * by; }

    // y[d] = sum_k a1[k]*W1[d][k] + a2[k]*W2[d][k]; k = 2*kk (+1): source lane kk
    for (int kk = 0; kk < 32; kk++) {
        float2 w1a = *(const float2*)&sW1[(2 * kk) * DIM + 2 * lane];
        float2 w2a = *(const float2*)&sW2[(2 * kk) * DIM + 2 * lane];
        float2 w1b = *(const float2*)&sW1[(2 * kk + 1) * DIM + 2 * lane];
        float2 w2b = *(const float2*)&sW2[(2 * kk + 1) * DIM + 2 * lane];
#pragma unroll
        for (int j = 0; j < NB; j++) {
            float a1a = __shfl_sync(0xffffffffu, a1x[j], kk);
            float a1b = __shfl_sync(0xffffffffu, a1y[j], kk);
            float a2a = __shfl_sync(0xffffffffu, a2x[j], kk);
            float a2b = __shfl_sync(0xffffffffu, a2y[j], kk);
            yx[j] += a1a * w1a.x + a2a * w2a.x + a1b * w1b.x + a2b * w2b.x;
            yy[j] += a1a * w1a.y + a2a * w2a.y + a1b * w1b.y + a2b * w2b.y;
        }
    }

#pragma unroll
    for (int j = 0; j < NB; j++) {
        int n = base + j;
        float vx = yx[j], vy = yy[j];
        vx = vx >= 0.f ? vx : 0.2f * vx;
        vy = vy >= 0.f ? vy : 0.2f * vy;
        float* o = out + (size_t)n * OUT_STRIDE + loff + DIM + 2 * lane;
        o[0] = vx;
        o[1] = vy;
    }
}

// ---------------- launch ----------------
extern "C" void kernel_launch(void* const* d_in, const int* in_sizes, int n_in,
                              void* d_out, int out_size) {
    const int* edge_index = (const int*)d_in[0];   // [2,E] int32
    const float* emb = (const float*)d_in[1];
    const float* W1 = (const float*)d_in[2];
    const float* b1 = (const float*)d_in[3];
    const float* W2 = (const float*)d_in[4];
    const float* b2 = (const float*)d_in[5];
    float* out = (float*)d_out;

    const int TB = 256;
    const int NBLK = (N_NODES + TB - 1) / TB;
    const int EBLK = (N_EDGES + TB - 1) / TB;

    init_kernel<<<NBLK, TB>>>();
    hist_kernel<<<EBLK, TB>>>(edge_index);
    dinv_kernel<<<NBLK, TB>>>();
    scan_a_kernel<<<SCAN_BLOCKS, SCAN_TB>>>();
    scan_b_kernel<<<1, 128>>>();
    scan_c_kernel<<<SCAN_BLOCKS, SCAN_TB>>>();
    scatter_kernel<<<EBLK, TB>>>(edge_index);

    copy_emb_kernel<<<(N_NODES * (DIM / 4) + TB - 1) / TB, TB>>>(emb, out);

    const int FBLK = N_NODES / (8 * NB);   // 3750 exact
    for (int l = 0; l < N_LAYERS; l++) {
        fused_layer_kernel<<<FBLK, 256>>>(
            W1 + l * DIM * DIM, b1 + l * DIM,
            W2 + l * DIM * DIM, b2 + l * DIM,
            out, l * DIM);
    }
}

// round 9
// speedup vs baseline: 1.1503x; 1.1503x over previous
#include <cuda_runtime.h>

#define N_NODES 120000
#define N_EDGES 1000000
#define DIM 64
#define N_LAYERS 3
#define OUT_STRIDE 256   // (N_LAYERS+1)*DIM
#define NB 8             // nodes per warp
#define SCAN_TB 1024
#define SCAN_BLOCKS ((N_NODES + SCAN_TB - 1) / SCAN_TB)  // 118

// ---------------- scratch ----------------
__device__ int   g_degcol[N_NODES];
__device__ int   g_degrow[N_NODES];
__device__ float g_dinv[N_NODES];
__device__ int   g_rowptr[N_NODES + 1];
__device__ int   g_cursor[N_NODES];
__device__ int   g_blocksum[SCAN_BLOCKS];
__device__ int2  g_edges[N_EDGES];   // CSR-ordered {col, __float_as_int(norm)}

// ---------------- setup ----------------
__global__ void init_kernel() {
    int i = blockIdx.x * blockDim.x + threadIdx.x;
    if (i < N_NODES) { g_degcol[i] = 0; g_degrow[i] = 0; }
}

__global__ void hist_kernel(const int* __restrict__ ei) {
    int e = blockIdx.x * blockDim.x + threadIdx.x;
    if (e >= N_EDGES) return;
    atomicAdd(&g_degrow[ei[e]], 1);
    atomicAdd(&g_degcol[ei[N_EDGES + e]], 1);
}

__global__ void dinv_kernel() {
    int i = blockIdx.x * blockDim.x + threadIdx.x;
    if (i >= N_NODES) return;
    int d = g_degcol[i];
    g_dinv[i] = (d > 0) ? rsqrtf((float)d) : 0.f;
}

__global__ void scan_a_kernel() {
    __shared__ int wsum[32];
    int tid = threadIdx.x, lane = tid & 31, wid = tid >> 5;
    int i = blockIdx.x * SCAN_TB + tid;
    int v = (i < N_NODES) ? g_degrow[i] : 0;
    int x = v;
#pragma unroll
    for (int off = 1; off < 32; off <<= 1) {
        int y = __shfl_up_sync(0xffffffffu, x, off);
        if (lane >= off) x += y;
    }
    if (lane == 31) wsum[wid] = x;
    __syncthreads();
    if (wid == 0) {
        int w = wsum[lane];
#pragma unroll
        for (int off = 1; off < 32; off <<= 1) {
            int y = __shfl_up_sync(0xffffffffu, w, off);
            if (lane >= off) w += y;
        }
        wsum[lane] = w;
    }
    __syncthreads();
    int excl = ((wid > 0) ? wsum[wid - 1] : 0) + x - v;
    if (i < N_NODES) g_rowptr[i] = excl;
    if (tid == SCAN_TB - 1) g_blocksum[blockIdx.x] = excl + v;
}

__global__ void scan_b_kernel() {
    __shared__ int ws[4];
    int tid = threadIdx.x, lane = tid & 31, wid = tid >> 5;
    int v = (tid < SCAN_BLOCKS) ? g_blocksum[tid] : 0;
    int x = v;
#pragma unroll
    for (int off = 1; off < 32; off <<= 1) {
        int y = __shfl_up_sync(0xffffffffu, x, off);
        if (lane >= off) x += y;
    }
    if (lane == 31) ws[wid] = x;
    __syncthreads();
    int carry = 0;
    for (int k = 0; k < wid; k++) carry += ws[k];
    if (tid < SCAN_BLOCKS) g_blocksum[tid] = carry + x - v;
}

__global__ void scan_c_kernel() {
    int i = blockIdx.x * SCAN_TB + threadIdx.x;
    if (i < N_NODES) {
        int r = g_rowptr[i] + g_blocksum[blockIdx.x];
        g_rowptr[i] = r;
        g_cursor[i] = r;
    }
    if (i == 0) g_rowptr[N_NODES] = N_EDGES;
}

__global__ void scatter_kernel(const int* __restrict__ ei) {
    int e = blockIdx.x * blockDim.x + threadIdx.x;
    if (e >= N_EDGES) return;
    int r = ei[e];
    int c = ei[N_EDGES + e];
    float nv = g_dinv[r] * g_dinv[c];
    int pos = atomicAdd(&g_cursor[r], 1);
    g_edges[pos] = make_int2(c, __float_as_int(nv));
}

__global__ void copy_emb_kernel(const float* __restrict__ emb, float* __restrict__ out) {
    int i = blockIdx.x * blockDim.x + threadIdx.x;
    if (i >= N_NODES * (DIM / 4)) return;
    int r = i >> 4;
    int q = i & 15;
    ((float4*)out)[(size_t)r * (OUT_STRIDE / 4) + q] = ((const float4*)emb)[i];
}

// ---------------- fused layer: CSR gather + shuffle GEMV + LeakyReLU ----------------
// 256 threads (8 warps); each warp owns NB=8 nodes. Lane handles dims {2*lane, 2*lane+1}.
// agg2 = xr (.) agg1, so only one accumulator per node is gathered.
__global__ __launch_bounds__(256) void fused_layer_kernel(
    const float* __restrict__ W1, const float* __restrict__ b1,
    const float* __restrict__ W2, const float* __restrict__ b2,
    float* __restrict__ out, int loff) {
    __shared__ float sW1[DIM * DIM];   // sW1[k*64 + d] = W1[d][k]
    __shared__ float sW2[DIM * DIM];
    __shared__ float sb[DIM];

    int tid = threadIdx.x;
    for (int i = tid; i < DIM * DIM; i += 256) {
        int d = i >> 6, k = i & 63;
        sW1[k * DIM + d] = W1[i];
        sW2[k * DIM + d] = W2[i];
    }
    if (tid < DIM) sb[tid] = b1[tid] + b2[tid];
    __syncthreads();

    int lane = tid & 31;
    int w = tid >> 5;
    int base = (blockIdx.x * 8 + w) * NB;
    const float* x = out + loff;

    float a1x[NB], a1y[NB], a2x[NB], a2y[NB], sv[NB];
#pragma unroll
    for (int j = 0; j < NB; j++) {
        a1x[j] = a1y[j] = a2x[j] = a2y[j] = sv[j] = 0.f;
        int n = base + j;
        if (n < N_NODES) {
            int s0 = g_rowptr[n], s1 = g_rowptr[n + 1];
            float2 xr = *(const float2*)(x + (size_t)n * OUT_STRIDE + 2 * lane);
            for (int e = s0; e < s1; e++) {
                int2 rec = g_edges[e];
                float nv = __int_as_float(rec.y);
                float2 xc = *(const float2*)(x + (size_t)rec.x * OUT_STRIDE + 2 * lane);
                a1x[j] += nv * xc.x;
                a1y[j] += nv * xc.y;
                sv[j] += nv;
            }
            a2x[j] = a1x[j] * xr.x;
            a2y[j] = a1y[j] * xr.y;
        }
    }

    float yx[NB], yy[NB];
    float bx = sb[2 * lane], by = sb[2 * lane + 1];
#pragma unroll
    for (int j = 0; j < NB; j++) { yx[j] = sv[j] * bx; yy[j] = sv[j] * by; }

    // y[d] = sum_k a1[k]*W1[d][k] + a2[k]*W2[d][k]; k = 2*kk (+1): source lane kk
    for (int kk = 0; kk < 32; kk++) {
        float2 w1a = *(const float2*)&sW1[(2 * kk) * DIM + 2 * lane];
        float2 w2a = *(const float2*)&sW2[(2 * kk) * DIM + 2 * lane];
        float2 w1b = *(const float2*)&sW1[(2 * kk + 1) * DIM + 2 * lane];
        float2 w2b = *(const float2*)&sW2[(2 * kk + 1) * DIM + 2 * lane];
#pragma unroll
        for (int j = 0; j < NB; j++) {
            float a1a = __shfl_sync(0xffffffffu, a1x[j], kk);
            float a1b = __shfl_sync(0xffffffffu, a1y[j], kk);
            float a2a = __shfl_sync(0xffffffffu, a2x[j], kk);
            float a2b = __shfl_sync(0xffffffffu, a2y[j], kk);
            yx[j] += a1a * w1a.x + a2a * w2a.x + a1b * w1b.x + a2b * w2b.x;
            yy[j] += a1a * w1a.y + a2a * w2a.y + a1b * w1b.y + a2b * w2b.y;
        }
    }

#pragma unroll
    for (int j = 0; j < NB; j++) {
        int n = base + j;
        if (n < N_NODES) {
            float vx = yx[j], vy = yy[j];
            vx = vx >= 0.f ? vx : 0.2f * vx;
            vy = vy >= 0.f ? vy : 0.2f * vy;
            float* o = out + (size_t)n * OUT_STRIDE + loff + DIM + 2 * lane;
            o[0] = vx;
            o[1] = vy;
        }
    }
}

// ---------------- launch ----------------
extern "C" void kernel_launch(void* const* d_in, const int* in_sizes, int n_in,
                              void* d_out, int out_size) {
    const int* edge_index = (const int*)d_in[0];   // [2,E] int32
    const float* emb = (const float*)d_in[1];
    const float* W1 = (const float*)d_in[2];
    const float* b1 = (const float*)d_in[3];
    const float* W2 = (const float*)d_in[4];
    const float* b2 = (const float*)d_in[5];
    float* out = (float*)d_out;

    const int TB = 256;
    const int NBLK = (N_NODES + TB - 1) / TB;
    const int EBLK = (N_EDGES + TB - 1) / TB;

    init_kernel<<<NBLK, TB>>>();
    hist_kernel<<<EBLK, TB>>>(edge_index);
    dinv_kernel<<<NBLK, TB>>>();
    scan_a_kernel<<<SCAN_BLOCKS, SCAN_TB>>>();
    scan_b_kernel<<<1, 128>>>();
    scan_c_kernel<<<SCAN_BLOCKS, SCAN_TB>>>();
    scatter_kernel<<<EBLK, TB>>>(edge_index);

    copy_emb_kernel<<<(N_NODES * (DIM / 4) + TB - 1) / TB, TB>>>(emb, out);

    const int FBLK = (N_NODES + 63) / 64;  // 1875
    for (int l = 0; l < N_LAYERS; l++) {
        fused_layer_kernel<<<FBLK, 256>>>(
            W1 + l * DIM * DIM, b1 + l * DIM,
            W2 + l * DIM * DIM, b2 + l * DIM,
            out, l * DIM);
    }
}

// round 10
// speedup vs baseline: 1.4062x; 1.2225x over previous
#include <cuda_runtime.h>

#define N_NODES 120000
#define N_EDGES 1000000
#define DIM 64
#define N_LAYERS 3
#define OUT_STRIDE 256   // (N_LAYERS+1)*DIM
#define NB 8             // nodes per warp
#define SCAN_TB 1024
#define SCAN_BLOCKS ((N_NODES + SCAN_TB - 1) / SCAN_TB)  // 118

typedef unsigned long long u64;

// ---------------- scratch ----------------
__device__ int   g_degcol[N_NODES];
__device__ int   g_degrow[N_NODES];
__device__ float g_dinv[N_NODES];
__device__ int   g_rowptr[N_NODES + 1];
__device__ int   g_cursor[N_NODES];
__device__ int   g_blocksum[SCAN_BLOCKS];
__device__ int2  g_edges[N_EDGES];   // CSR-ordered {col, __float_as_int(norm)}

// ---------------- packed f32x2 helpers (validated in R5/R6) ----------------
__device__ __forceinline__ u64 fma2(u64 a, u64 b, u64 c) {
    u64 d;
    asm("fma.rn.f32x2 %0, %1, %2, %3;" : "=l"(d) : "l"(a), "l"(b), "l"(c));
    return d;
}
__device__ __forceinline__ u64 pack2(float lo, float hi) {
    u64 d;
    asm("mov.b64 %0, {%1, %2};" : "=l"(d) : "f"(lo), "f"(hi));
    return d;
}
__device__ __forceinline__ u64 dup2(float v) {
    u64 d;
    asm("mov.b64 %0, {%1, %1};" : "=l"(d) : "f"(v));
    return d;
}
__device__ __forceinline__ float2 unpack2(u64 v) {
    float lo, hi;
    asm("mov.b64 {%0, %1}, %2;" : "=f"(lo), "=f"(hi) : "l"(v));
    return make_float2(lo, hi);
}

// ---------------- setup ----------------
__global__ void init_kernel() {
    int i = blockIdx.x * blockDim.x + threadIdx.x;
    if (i < N_NODES) { g_degcol[i] = 0; g_degrow[i] = 0; }
}

__global__ void hist_kernel(const int* __restrict__ ei) {
    int e = blockIdx.x * blockDim.x + threadIdx.x;
    if (e >= N_EDGES) return;
    atomicAdd(&g_degrow[ei[e]], 1);
    atomicAdd(&g_degcol[ei[N_EDGES + e]], 1);
}

__global__ void dinv_kernel() {
    int i = blockIdx.x * blockDim.x + threadIdx.x;
    if (i >= N_NODES) return;
    int d = g_degcol[i];
    g_dinv[i] = (d > 0) ? rsqrtf((float)d) : 0.f;
}

__global__ void scan_a_kernel() {
    __shared__ int wsum[32];
    int tid = threadIdx.x, lane = tid & 31, wid = tid >> 5;
    int i = blockIdx.x * SCAN_TB + tid;
    int v = (i < N_NODES) ? g_degrow[i] : 0;
    int x = v;
#pragma unroll
    for (int off = 1; off < 32; off <<= 1) {
        int y = __shfl_up_sync(0xffffffffu, x, off);
        if (lane >= off) x += y;
    }
    if (lane == 31) wsum[wid] = x;
    __syncthreads();
    if (wid == 0) {
        int w = wsum[lane];
#pragma unroll
        for (int off = 1; off < 32; off <<= 1) {
            int y = __shfl_up_sync(0xffffffffu, w, off);
            if (lane >= off) w += y;
        }
        wsum[lane] = w;
    }
    __syncthreads();
    int excl = ((wid > 0) ? wsum[wid - 1] : 0) + x - v;
    if (i < N_NODES) g_rowptr[i] = excl;
    if (tid == SCAN_TB - 1) g_blocksum[blockIdx.x] = excl + v;
}

__global__ void scan_b_kernel() {
    __shared__ int ws[4];
    int tid = threadIdx.x, lane = tid & 31, wid = tid >> 5;
    int v = (tid < SCAN_BLOCKS) ? g_blocksum[tid] : 0;
    int x = v;
#pragma unroll
    for (int off = 1; off < 32; off <<= 1) {
        int y = __shfl_up_sync(0xffffffffu, x, off);
        if (lane >= off) x += y;
    }
    if (lane == 31) ws[wid] = x;
    __syncthreads();
    int carry = 0;
    for (int k = 0; k < wid; k++) carry += ws[k];
    if (tid < SCAN_BLOCKS) g_blocksum[tid] = carry + x - v;
}

__global__ void scan_c_kernel() {
    int i = blockIdx.x * SCAN_TB + threadIdx.x;
    if (i < N_NODES) {
        int r = g_rowptr[i] + g_blocksum[blockIdx.x];
        g_rowptr[i] = r;
        g_cursor[i] = r;
    }
    if (i == 0) g_rowptr[N_NODES] = N_EDGES;
}

__global__ void scatter_kernel(const int* __restrict__ ei) {
    int e = blockIdx.x * blockDim.x + threadIdx.x;
    if (e >= N_EDGES) return;
    int r = ei[e];
    int c = ei[N_EDGES + e];
    float nv = g_dinv[r] * g_dinv[c];
    int pos = atomicAdd(&g_cursor[r], 1);
    g_edges[pos] = make_int2(c, __float_as_int(nv));
}

__global__ void copy_emb_kernel(const float* __restrict__ emb, float* __restrict__ out) {
    int i = blockIdx.x * blockDim.x + threadIdx.x;
    if (i >= N_NODES * (DIM / 4)) return;
    int r = i >> 4;
    int q = i & 15;
    ((float4*)out)[(size_t)r * (OUT_STRIDE / 4) + q] = ((const float4*)emb)[i];
}

// ---------------- fused layer: CSR gather + smem-staged FFMA2 GEMV + LeakyReLU ----------------
// 256 threads (8 warps); each warp owns NB=8 nodes. Lane handles dims {2*lane, 2*lane+1}.
// agg2 = xr (.) agg1 -> single gathered accumulator; staged as (a1,a2) float2 per k in smem.
// GEMV: broadcast LDS.64 of (a1[k],a2[k]) + register dup + fma.rn.f32x2 (no shuffles).
__global__ __launch_bounds__(256) void fused_layer_kernel(
    const float* __restrict__ W1, const float* __restrict__ b1,
    const float* __restrict__ W2, const float* __restrict__ b2,
    float* __restrict__ out, int loff) {
    extern __shared__ char smem[];
    float* sW1 = (float*)smem;             // [k*64 + d] = W1[d][k]  (16 KB)
    float* sW2 = sW1 + DIM * DIM;          // (16 KB)
    float* sb = sW2 + DIM * DIM;           // 64 floats
    float2* sacc = (float2*)(sb + DIM);    // [8 warps][NB][64] float2 (a1[k], a2[k])  (32 KB)

    int tid = threadIdx.x;
    for (int i = tid; i < DIM * DIM; i += 256) {
        int d = i >> 6, k = i & 63;
        sW1[k * DIM + d] = W1[i];
        sW2[k * DIM + d] = W2[i];
    }
    if (tid < DIM) sb[tid] = b1[tid] + b2[tid];
    __syncthreads();

    int lane = tid & 31;
    int w = tid >> 5;
    int base = (blockIdx.x * 8 + w) * NB;  // grid exact: 1875*64 = 120000
    const float* x = out + loff;
    float2* macc = sacc + (size_t)w * (NB * DIM);

    float sv[NB];
#pragma unroll
    for (int j = 0; j < NB; j++) {
        float ax = 0.f, ay = 0.f, s = 0.f;
        int n = base + j;
        int s0 = g_rowptr[n], s1 = g_rowptr[n + 1];
        float2 xr = *(const float2*)(x + (size_t)n * OUT_STRIDE + 2 * lane);
        for (int e = s0; e < s1; e++) {
            int2 rec = g_edges[e];
            float nv = __int_as_float(rec.y);
            float2 xc = *(const float2*)(x + (size_t)rec.x * OUT_STRIDE + 2 * lane);
            ax += nv * xc.x;
            ay += nv * xc.y;
            s += nv;
        }
        sv[j] = s;
        // stage (a1[2l],a2[2l],a1[2l+1],a2[2l+1]) as one STS.128, conflict-free
        *(float4*)&macc[j * DIM + 2 * lane] = make_float4(ax, ax * xr.x, ay, ay * xr.y);
    }
    __syncwarp();

    const u64* sW1p = (const u64*)sW1;   // [k*32+lane] = (W1[2l][k], W1[2l+1][k])
    const u64* sW2p = (const u64*)sW2;
    float2 bf = unpack2(((const u64*)sb)[lane]);
    u64 y[NB];
#pragma unroll
    for (int j = 0; j < NB; j++) y[j] = pack2(sv[j] * bf.x, sv[j] * bf.y);

#pragma unroll 8
    for (int k = 0; k < DIM; k++) {
        u64 w1 = sW1p[k * 32 + lane];
        u64 w2 = sW2p[k * 32 + lane];
#pragma unroll
        for (int j = 0; j < NB; j++) {
            float2 a = macc[j * DIM + k];   // broadcast LDS.64
            y[j] = fma2(dup2(a.x), w1, y[j]);
            y[j] = fma2(dup2(a.y), w2, y[j]);
        }
    }

#pragma unroll
    for (int j = 0; j < NB; j++) {
        int n = base + j;
        float2 v = unpack2(y[j]);
        v.x = v.x >= 0.f ? v.x : 0.2f * v.x;
        v.y = v.y >= 0.f ? v.y : 0.2f * v.y;
        *(float2*)(out + (size_t)n * OUT_STRIDE + loff + DIM + 2 * lane) = v;
    }
}

// ---------------- launch ----------------
extern "C" void kernel_launch(void* const* d_in, const int* in_sizes, int n_in,
                              void* d_out, int out_size) {
    const int* edge_index = (const int*)d_in[0];   // [2,E] int32
    const float* emb = (const float*)d_in[1];
    const float* W1 = (const float*)d_in[2];
    const float* b1 = (const float*)d_in[3];
    const float* W2 = (const float*)d_in[4];
    const float* b2 = (const float*)d_in[5];
    float* out = (float*)d_out;

    const int TB = 256;
    const int NBLK = (N_NODES + TB - 1) / TB;
    const int EBLK = (N_EDGES + TB - 1) / TB;

    init_kernel<<<NBLK, TB>>>();
    hist_kernel<<<EBLK, TB>>>(edge_index);
    dinv_kernel<<<NBLK, TB>>>();
    scan_a_kernel<<<SCAN_BLOCKS, SCAN_TB>>>();
    scan_b_kernel<<<1, 128>>>();
    scan_c_kernel<<<SCAN_BLOCKS, SCAN_TB>>>();
    scatter_kernel<<<EBLK, TB>>>(edge_index);

    copy_emb_kernel<<<(N_NODES * (DIM / 4) + TB - 1) / TB, TB>>>(emb, out);

    // dynamic smem: weights 32.25 KB + acc staging 32 KB = 64.25 KB -> 3 blocks/SM (same as R9)
    const int SMEM_BYTES = (2 * DIM * DIM + DIM) * 4 + 8 * NB * DIM * 8;  // 65792
    cudaFuncSetAttribute(fused_layer_kernel, cudaFuncAttributeMaxDynamicSharedMemorySize, SMEM_BYTES);

    const int FBLK = N_NODES / 64;  // 1875 exact
    for (int l = 0; l < N_LAYERS; l++) {
        fused_layer_kernel<<<FBLK, 256, SMEM_BYTES>>>(
            W1 + l * DIM * DIM, b1 + l * DIM,
            W2 + l * DIM * DIM, b2 + l * DIM,
            out, l * DIM);
    }
}

// round 11
// speedup vs baseline: 1.4346x; 1.0202x over previous
#include <cuda_runtime.h>

#define N_NODES 120000
#define N_EDGES 1000000
#define DIM 64
#define N_LAYERS 3
#define OUT_STRIDE 256   // (N_LAYERS+1)*DIM
#define NB 8             // nodes per warp
#define SCAN_TB 1024
#define SCAN_BLOCKS ((N_NODES + SCAN_TB - 1) / SCAN_TB)  // 118

typedef unsigned long long u64;

// ---------------- scratch ----------------
__device__ int   g_degcol[N_NODES];
__device__ int   g_degrow[N_NODES];
__device__ float g_dinv[N_NODES];
__device__ int   g_rowptr[N_NODES + 1];
__device__ int   g_cursor[N_NODES];
__device__ int   g_blocksum[SCAN_BLOCKS];
__device__ int2  g_edges[N_EDGES];   // CSR-ordered {col, __float_as_int(norm)}

// ---------------- packed f32x2 helpers ----------------
__device__ __forceinline__ u64 fma2(u64 a, u64 b, u64 c) {
    u64 d;
    asm("fma.rn.f32x2 %0, %1, %2, %3;" : "=l"(d) : "l"(a), "l"(b), "l"(c));
    return d;
}
__device__ __forceinline__ u64 pack2(float lo, float hi) {
    u64 d;
    asm("mov.b64 %0, {%1, %2};" : "=l"(d) : "f"(lo), "f"(hi));
    return d;
}
__device__ __forceinline__ u64 dup2(float v) {
    u64 d;
    asm("mov.b64 %0, {%1, %1};" : "=l"(d) : "f"(v));
    return d;
}
__device__ __forceinline__ float2 unpack2(u64 v) {
    float lo, hi;
    asm("mov.b64 {%0, %1}, %2;" : "=f"(lo), "=f"(hi) : "l"(v));
    return make_float2(lo, hi);
}

// ---------------- setup ----------------
__global__ void init_kernel() {
    int i = blockIdx.x * blockDim.x + threadIdx.x;
    if (i < N_NODES) { g_degcol[i] = 0; g_degrow[i] = 0; }
}

__global__ void hist_kernel(const int* __restrict__ ei) {
    int e = blockIdx.x * blockDim.x + threadIdx.x;
    if (e >= N_EDGES) return;
    atomicAdd(&g_degrow[ei[e]], 1);
    atomicAdd(&g_degcol[ei[N_EDGES + e]], 1);
}

__global__ void dinv_kernel() {
    int i = blockIdx.x * blockDim.x + threadIdx.x;
    if (i >= N_NODES) return;
    int d = g_degcol[i];
    g_dinv[i] = (d > 0) ? rsqrtf((float)d) : 0.f;
}

__global__ void scan_a_kernel() {
    __shared__ int wsum[32];
    int tid = threadIdx.x, lane = tid & 31, wid = tid >> 5;
    int i = blockIdx.x * SCAN_TB + tid;
    int v = (i < N_NODES) ? g_degrow[i] : 0;
    int x = v;
#pragma unroll
    for (int off = 1; off < 32; off <<= 1) {
        int y = __shfl_up_sync(0xffffffffu, x, off);
        if (lane >= off) x += y;
    }
    if (lane == 31) wsum[wid] = x;
    __syncthreads();
    if (wid == 0) {
        int w = wsum[lane];
#pragma unroll
        for (int off = 1; off < 32; off <<= 1) {
            int y = __shfl_up_sync(0xffffffffu, w, off);
            if (lane >= off) w += y;
        }
        wsum[lane] = w;
    }
    __syncthreads();
    int excl = ((wid > 0) ? wsum[wid - 1] : 0) + x - v;
    if (i < N_NODES) g_rowptr[i] = excl;
    if (tid == SCAN_TB - 1) g_blocksum[blockIdx.x] = excl + v;
}

__global__ void scan_b_kernel() {
    __shared__ int ws[4];
    int tid = threadIdx.x, lane = tid & 31, wid = tid >> 5;
    int v = (tid < SCAN_BLOCKS) ? g_blocksum[tid] : 0;
    int x = v;
#pragma unroll
    for (int off = 1; off < 32; off <<= 1) {
        int y = __shfl_up_sync(0xffffffffu, x, off);
        if (lane >= off) x += y;
    }
    if (lane == 31) ws[wid] = x;
    __syncthreads();
    int carry = 0;
    for (int k = 0; k < wid; k++) carry += ws[k];
    if (tid < SCAN_BLOCKS) g_blocksum[tid] = carry + x - v;
}

__global__ void scan_c_kernel() {
    int i = blockIdx.x * SCAN_TB + threadIdx.x;
    if (i < N_NODES) {
        int r = g_rowptr[i] + g_blocksum[blockIdx.x];
        g_rowptr[i] = r;
        g_cursor[i] = r;
    }
    if (i == 0) g_rowptr[N_NODES] = N_EDGES;
}

__global__ void scatter_kernel(const int* __restrict__ ei) {
    int e = blockIdx.x * blockDim.x + threadIdx.x;
    if (e >= N_EDGES) return;
    int r = ei[e];
    int c = ei[N_EDGES + e];
    float nv = g_dinv[r] * g_dinv[c];
    int pos = atomicAdd(&g_cursor[r], 1);
    g_edges[pos] = make_int2(c, __float_as_int(nv));
}

__global__ void copy_emb_kernel(const float* __restrict__ emb, float* __restrict__ out) {
    int i = blockIdx.x * blockDim.x + threadIdx.x;
    if (i >= N_NODES * (DIM / 4)) return;
    int r = i >> 4;
    int q = i & 15;
    ((float4*)out)[(size_t)r * (OUT_STRIDE / 4) + q] = ((const float4*)emb)[i];
}

// ---------------- fused layer: CSR gather (x2 unroll) + smem FFMA2 GEMV + LeakyReLU ----------------
// 256 threads (8 warps); each warp owns NB=8 nodes. Lane handles dims {2*lane, 2*lane+1}.
// Weights staged interleaved: one LDS.128 per k yields (W1 pair, W2 pair) as two u64.
__global__ __launch_bounds__(256) void fused_layer_kernel(
    const float* __restrict__ W1, const float* __restrict__ b1,
    const float* __restrict__ W2, const float* __restrict__ b2,
    float* __restrict__ out, int loff) {
    extern __shared__ char smem[];
    float* sW = (float*)smem;              // [k*32+l] float4 = (W1[2l][k],W1[2l+1][k],W2[2l][k],W2[2l+1][k])  32KB
    float* sb = sW + 2 * DIM * DIM;        // 64 floats
    float2* sacc = (float2*)(sb + DIM);    // [8 warps][NB][64] float2 (a1[k], a2[k])  32KB

    int tid = threadIdx.x;
    for (int i = tid; i < DIM * DIM; i += 256) {
        int d = i >> 6, k = i & 63;
        int slot = (k * 32 + (d >> 1)) * 4 + (d & 1);
        sW[slot] = W1[i];
        sW[slot + 2] = W2[i];
    }
    if (tid < DIM) sb[tid] = b1[tid] + b2[tid];
    __syncthreads();

    int lane = tid & 31;
    int w = tid >> 5;
    int base = (blockIdx.x * 8 + w) * NB;  // grid exact: 1875*64 = 120000
    const float* x = out + loff;
    float2* macc = sacc + (size_t)w * (NB * DIM);

    float sv[NB];
#pragma unroll
    for (int j = 0; j < NB; j++) {
        float ax = 0.f, ay = 0.f, s = 0.f;
        int n = base + j;
        int s0 = g_rowptr[n], s1 = g_rowptr[n + 1];
        float2 xr = *(const float2*)(x + (size_t)n * OUT_STRIDE + 2 * lane);
        int e = s0;
        // two independent rec->x chains in flight
        for (; e + 2 <= s1; e += 2) {
            int2 rA = g_edges[e];
            int2 rB = g_edges[e + 1];
            float2 xA = *(const float2*)(x + (size_t)rA.x * OUT_STRIDE + 2 * lane);
            float2 xB = *(const float2*)(x + (size_t)rB.x * OUT_STRIDE + 2 * lane);
            float nA = __int_as_float(rA.y), nB = __int_as_float(rB.y);
            ax += nA * xA.x + nB * xB.x;
            ay += nA * xA.y + nB * xB.y;
            s += nA + nB;
        }
        if (e < s1) {
            int2 rec = g_edges[e];
            float nv = __int_as_float(rec.y);
            float2 xc = *(const float2*)(x + (size_t)rec.x * OUT_STRIDE + 2 * lane);
            ax += nv * xc.x;
            ay += nv * xc.y;
            s += nv;
        }
        sv[j] = s;
        // stage (a1[2l],a2[2l],a1[2l+1],a2[2l+1]) as one STS.128, conflict-free
        *(float4*)&macc[j * DIM + 2 * lane] = make_float4(ax, ax * xr.x, ay, ay * xr.y);
    }
    __syncwarp();

    const ulonglong2* sWp = (const ulonglong2*)sW;  // [k*32+lane] = {w1 pair, w2 pair}
    float2 bf = unpack2(((const u64*)sb)[lane]);
    u64 y[NB];
#pragma unroll
    for (int j = 0; j < NB; j++) y[j] = pack2(sv[j] * bf.x, sv[j] * bf.y);

#pragma unroll 8
    for (int k = 0; k < DIM; k++) {
        ulonglong2 wq = sWp[k * 32 + lane];   // one LDS.128: w1 pair + w2 pair
#pragma unroll
        for (int j = 0; j < NB; j++) {
            float2 a = macc[j * DIM + k];     // broadcast LDS.64
            y[j] = fma2(dup2(a.x), wq.x, y[j]);
            y[j] = fma2(dup2(a.y), wq.y, y[j]);
        }
    }

#pragma unroll
    for (int j = 0; j < NB; j++) {
        int n = base + j;
        float2 v = unpack2(y[j]);
        v.x = v.x >= 0.f ? v.x : 0.2f * v.x;
        v.y = v.y >= 0.f ? v.y : 0.2f * v.y;
        *(float2*)(out + (size_t)n * OUT_STRIDE + loff + DIM + 2 * lane) = v;
    }
}

// ---------------- launch ----------------
extern "C" void kernel_launch(void* const* d_in, const int* in_sizes, int n_in,
                              void* d_out, int out_size) {
    const int* edge_index = (const int*)d_in[0];   // [2,E] int32
    const float* emb = (const float*)d_in[1];
    const float* W1 = (const float*)d_in[2];
    const float* b1 = (const float*)d_in[3];
    const float* W2 = (const float*)d_in[4];
    const float* b2 = (const float*)d_in[5];
    float* out = (float*)d_out;

    const int TB = 256;
    const int NBLK = (N_NODES + TB - 1) / TB;
    const int EBLK = (N_EDGES + TB - 1) / TB;

    init_kernel<<<NBLK, TB>>>();
    hist_kernel<<<EBLK, TB>>>(edge_index);
    dinv_kernel<<<NBLK, TB>>>();
    scan_a_kernel<<<SCAN_BLOCKS, SCAN_TB>>>();
    scan_b_kernel<<<1, 128>>>();
    scan_c_kernel<<<SCAN_BLOCKS, SCAN_TB>>>();
    scatter_kernel<<<EBLK, TB>>>(edge_index);

    copy_emb_kernel<<<(N_NODES * (DIM / 4) + TB - 1) / TB, TB>>>(emb, out);

    // dynamic smem: weights 32.25 KB + acc staging 32 KB = 64.25 KB -> 3 blocks/SM
    const int SMEM_BYTES = (2 * DIM * DIM + DIM) * 4 + 8 * NB * DIM * 8;  // 65792
    cudaFuncSetAttribute(fused_layer_kernel, cudaFuncAttributeMaxDynamicSharedMemorySize, SMEM_BYTES);

    const int FBLK = N_NODES / 64;  // 1875 exact
    for (int l = 0; l < N_LAYERS; l++) {
        fused_layer_kernel<<<FBLK, 256, SMEM_BYTES>>>(
            W1 + l * DIM * DIM, b1 + l * DIM,
            W2 + l * DIM * DIM, b2 + l * DIM,
            out, l * DIM);
    }
}